// round 11
// baseline (speedup 1.0000x reference)
#include <cuda_runtime.h>

// Problem constants
#define B_SZ   4096
#define E_SZ   128
#define IP_SZ  64
#define H_SZ   100
#define HP     128      // padded weight-tile column stride
#define ROWS   128      // batch rows per CTA
#define THREADS 1024    // 32 warps: 16 warps x 2 column-halves, 4 row-pairs each
#define XPS    66       // pair-stride of xP planes (even -> 16B-aligned LDS.128)
#define HPS    66       // pair-stride of hP2 (k-major) planes

// ---------- f32x2 packed helpers ----------
__device__ __forceinline__ unsigned long long pk2(float a, float b) {
    unsigned long long d;
    asm("mov.b64 %0, {%1, %2};" : "=l"(d) : "f"(a), "f"(b));
    return d;
}
__device__ __forceinline__ float2 upk2(unsigned long long v) {
    float2 r;
    asm("mov.b64 {%0, %1}, %2;" : "=f"(r.x), "=f"(r.y) : "l"(v));
    return r;
}
__device__ __forceinline__ unsigned long long ffma2(unsigned long long a,
                                                    unsigned long long b,
                                                    unsigned long long c) {
    unsigned long long d;
    asm("fma.rn.f32x2 %0, %1, %2, %3;" : "=l"(d) : "l"(a), "l"(b), "l"(c));
    return d;
}

// Shared memory (floats):
//   W1P  : 64*128          = 8192
//   W2P  : 100*128         = 12800
//   vec  : 704   (b1|g1|be1|b2|g2|be2|Wo @ 100 each, bo @ 700)
//   xPf  : 64*66*2         = 8448   (packed (even,odd) pair per (i, rp))
//   hPf  : 100*66*2        = 13200  (k-major packed pairs: hP2[k][rp])
//   red  : 64*2*4          = 512    (LN partials: s.x,s.y,q.x,q.y per rp/half)
//   head : 64*2*2          = 256    (head partials per rp/half)
#define SMEM_FLOATS (8192 + 12800 + 704 + 8448 + 13200 + 512 + 256)

__global__ __launch_bounds__(THREADS, 1)
void fused_edge_mlp_kernel(
    const float* __restrict__ gx,  const float* __restrict__ gW1,
    const float* __restrict__ gb1, const float* __restrict__ gg1,
    const float* __restrict__ gbe1,const float* __restrict__ gW2,
    const float* __restrict__ gb2, const float* __restrict__ gg2,
    const float* __restrict__ gbe2,const float* __restrict__ gWo,
    const float* __restrict__ gbo, float* __restrict__ out)
{
    extern __shared__ float sm[];
    float* W1P  = sm;                         // [64][128]
    float* W2P  = W1P + 64 * HP;              // [100][128]
    float* vec  = W2P + H_SZ * HP;            // 704
    float* xPf  = vec + 704;                  // [64][66] pairs
    float* hPf  = xPf + 64 * XPS * 2;         // [100][66] pairs (k-major)
    float* red  = hPf + H_SZ * HPS * 2;       // [64][2] float4 slots
    float* head = red + 64 * 2 * 4;           // [64][2] float2 slots
    unsigned long long* xP  = (unsigned long long*)xPf;
    unsigned long long* hP2 = (unsigned long long*)hPf;

    const int e   = blockIdx.x;
    const int b0  = blockIdx.y * ROWS;
    const int tid = threadIdx.x;

    // ---- stage weights (vectorized, zero-padded to 128 cols) ----
    {
        const float4* w1v = (const float4*)(gW1 + (size_t)e * IP_SZ * H_SZ);
        for (int idx = tid; idx < IP_SZ * 25; idx += THREADS) {
            int i = idx / 25, c4 = idx % 25;
            float4 v = w1v[idx];
            float* dst = &W1P[i * HP + c4 * 4];
            dst[0] = v.x; dst[1] = v.y; dst[2] = v.z; dst[3] = v.w;
        }
        for (int idx = tid; idx < IP_SZ * 28; idx += THREADS) {
            int i = idx / 28, jj = 100 + idx % 28;
            W1P[i * HP + jj] = 0.f;
        }
        const float4* w2v = (const float4*)(gW2 + (size_t)e * H_SZ * H_SZ);
        for (int idx = tid; idx < H_SZ * 25; idx += THREADS) {
            int i = idx / 25, c4 = idx % 25;
            float4 v = w2v[idx];
            float* dst = &W2P[i * HP + c4 * 4];
            dst[0] = v.x; dst[1] = v.y; dst[2] = v.z; dst[3] = v.w;
        }
        for (int idx = tid; idx < H_SZ * 28; idx += THREADS) {
            int i = idx / 28, jj = 100 + idx % 28;
            W2P[i * HP + jj] = 0.f;
        }
        if (tid < H_SZ) {
            vec[           tid] = gb1 [e * H_SZ + tid];
            vec[1 * H_SZ + tid] = gg1 [e * H_SZ + tid];
            vec[2 * H_SZ + tid] = gbe1[e * H_SZ + tid];
            vec[3 * H_SZ + tid] = gb2 [e * H_SZ + tid];
            vec[4 * H_SZ + tid] = gg2 [e * H_SZ + tid];
            vec[5 * H_SZ + tid] = gbe2[e * H_SZ + tid];
            vec[6 * H_SZ + tid] = gWo [e * H_SZ + tid];
        }
        if (tid == 0) vec[700] = gbo[e];

        // ---- stage x into packed (even,odd) row-pair planes: xP[i][rp] ----
        const float4* gx4 = (const float4*)gx;
        for (int idx = tid; idx < ROWS * 16; idx += THREADS) {
            int r = idx >> 4, i4 = idx & 15;
            float4 v = gx4[(((size_t)(b0 + r) * E_SZ + e) * IP_SZ >> 2) + i4];
            int rp = r >> 1, hr = r & 1;
            int i = i4 * 4;
            xPf[((i + 0) * XPS + rp) * 2 + hr] = v.x;
            xPf[((i + 1) * XPS + rp) * 2 + hr] = v.y;
            xPf[((i + 2) * XPS + rp) * 2 + hr] = v.z;
            xPf[((i + 3) * XPS + rp) * 2 + hr] = v.w;
        }
    }
    __syncthreads();

    const int warp  = tid >> 5;
    const int lane  = tid & 31;
    const int half  = warp >> 4;        // 0: cols [0,64), 1: cols [64,128)
    const int wl    = warp & 15;
    const int pbase = wl * 4;           // first row-pair of this warp

    const int  j0  = half * 64 + lane;          // always valid (<100)
    const int  j1  = half * 64 + 32 + lane;     // valid unless half==1 && lane>=4
    const bool jv1 = (half == 0) || (lane < 4);

    unsigned long long acc[4][2];
#pragma unroll
    for (int p = 0; p < 4; p++) { acc[p][0] = 0ull; acc[p][1] = 0ull; }

    const float* wcol1 = W1P + half * 64 + lane;   // + i*HP (+32)
    const float* wcol2 = W2P + half * 64 + lane;   // + k*HP (+32)

    // ---- layer 1 mainloop: over K=64 ----
#pragma unroll 8
    for (int i = 0; i < IP_SZ; i++) {
        ulonglong2 xa = *(const ulonglong2*)(xP + i * XPS + pbase);
        ulonglong2 xb = *(const ulonglong2*)(xP + i * XPS + pbase + 2);
        float w0 = wcol1[i * HP];
        float w1 = wcol1[i * HP + 32];
        unsigned long long wd0 = pk2(w0, w0);
        unsigned long long wd1 = pk2(w1, w1);
        acc[0][0] = ffma2(xa.x, wd0, acc[0][0]);
        acc[1][0] = ffma2(xa.y, wd0, acc[1][0]);
        acc[2][0] = ffma2(xb.x, wd0, acc[2][0]);
        acc[3][0] = ffma2(xb.y, wd0, acc[3][0]);
        acc[0][1] = ffma2(xa.x, wd1, acc[0][1]);
        acc[1][1] = ffma2(xa.y, wd1, acc[1][1]);
        acc[2][1] = ffma2(xb.x, wd1, acc[2][1]);
        acc[3][1] = ffma2(xb.y, wd1, acc[3][1]);
    }

    // ---- layer-1 epilogue: bias + leaky + cross-half LN -> hP2 (k-major) ----
    float2 a0s[4], a1s[4];
#pragma unroll
    for (int p = 0; p < 4; p++) {
        float2 a0 = upk2(acc[p][0]);
        float2 a1 = upk2(acc[p][1]);
        float bb0 = vec[j0];
        a0.x += bb0; a0.y += bb0;
        a0.x = a0.x > 0.f ? a0.x : 0.01f * a0.x;
        a0.y = a0.y > 0.f ? a0.y : 0.01f * a0.y;
        float2 s = a0, q = make_float2(a0.x * a0.x, a0.y * a0.y);
        if (jv1) {
            float bb1 = vec[j1];
            a1.x += bb1; a1.y += bb1;
            a1.x = a1.x > 0.f ? a1.x : 0.01f * a1.x;
            a1.y = a1.y > 0.f ? a1.y : 0.01f * a1.y;
            s.x += a1.x; s.y += a1.y;
            q.x += a1.x * a1.x; q.y += a1.y * a1.y;
        } else { a1.x = 0.f; a1.y = 0.f; }
#pragma unroll
        for (int m = 16; m; m >>= 1) {
            s.x += __shfl_xor_sync(0xffffffffu, s.x, m);
            s.y += __shfl_xor_sync(0xffffffffu, s.y, m);
            q.x += __shfl_xor_sync(0xffffffffu, q.x, m);
            q.y += __shfl_xor_sync(0xffffffffu, q.y, m);
        }
        if (lane == 0) {
            float4* slot = (float4*)(red + ((pbase + p) * 2 + half) * 4);
            *slot = make_float4(s.x, s.y, q.x, q.y);
        }
        a0s[p] = a0; a1s[p] = a1;
        acc[p][0] = 0ull; acc[p][1] = 0ull;
    }
    __syncthreads();
#pragma unroll
    for (int p = 0; p < 4; p++) {
        float4 r0 = *(const float4*)(red + ((pbase + p) * 2 + 0) * 4);
        float4 r1 = *(const float4*)(red + ((pbase + p) * 2 + 1) * 4);
        const float inv = 1.0f / (float)H_SZ;
        float mx = (r0.x + r1.x) * inv, my = (r0.y + r1.y) * inv;
        float vx = (r0.z + r1.z) * inv - mx * mx;
        float vy = (r0.w + r1.w) * inv - my * my;
        float rx = rsqrtf(vx + 1e-5f), ry = rsqrtf(vy + 1e-5f);
        float g0 = vec[100 + j0], bt0 = vec[200 + j0];
        float h0x = (a0s[p].x - mx) * rx * g0 + bt0;
        float h0y = (a0s[p].y - my) * ry * g0 + bt0;
        hP2[(size_t)j0 * HPS + pbase + p] = pk2(h0x, h0y);
        if (jv1) {
            float g1v = vec[100 + j1], bt1 = vec[200 + j1];
            float h1x = (a1s[p].x - mx) * rx * g1v + bt1;
            float h1y = (a1s[p].y - my) * ry * g1v + bt1;
            hP2[(size_t)j1 * HPS + pbase + p] = pk2(h1x, h1y);
        }
    }
    __syncthreads();

    // ---- layer 2 mainloop: over K=100 ----
#pragma unroll 4
    for (int k = 0; k < H_SZ; k++) {
        ulonglong2 xa = *(const ulonglong2*)(hP2 + (size_t)k * HPS + pbase);
        ulonglong2 xb = *(const ulonglong2*)(hP2 + (size_t)k * HPS + pbase + 2);
        float w0 = wcol2[k * HP];
        float w1 = wcol2[k * HP + 32];
        unsigned long long wd0 = pk2(w0, w0);
        unsigned long long wd1 = pk2(w1, w1);
        acc[0][0] = ffma2(xa.x, wd0, acc[0][0]);
        acc[1][0] = ffma2(xa.y, wd0, acc[1][0]);
        acc[2][0] = ffma2(xb.x, wd0, acc[2][0]);
        acc[3][0] = ffma2(xb.y, wd0, acc[3][0]);
        acc[0][1] = ffma2(xa.x, wd1, acc[0][1]);
        acc[1][1] = ffma2(xa.y, wd1, acc[1][1]);
        acc[2][1] = ffma2(xb.x, wd1, acc[2][1]);
        acc[3][1] = ffma2(xb.y, wd1, acc[3][1]);
    }

    // ---- layer-2 epilogue: bias + leaky + cross-half LN + head ----
#pragma unroll
    for (int p = 0; p < 4; p++) {
        float2 a0 = upk2(acc[p][0]);
        float2 a1 = upk2(acc[p][1]);
        float bb0 = vec[300 + j0];
        a0.x += bb0; a0.y += bb0;
        a0.x = a0.x > 0.f ? a0.x : 0.01f * a0.x;
        a0.y = a0.y > 0.f ? a0.y : 0.01f * a0.y;
        float2 s = a0, q = make_float2(a0.x * a0.x, a0.y * a0.y);
        if (jv1) {
            float bb1 = vec[300 + j1];
            a1.x += bb1; a1.y += bb1;
            a1.x = a1.x > 0.f ? a1.x : 0.01f * a1.x;
            a1.y = a1.y > 0.f ? a1.y : 0.01f * a1.y;
            s.x += a1.x; s.y += a1.y;
            q.x += a1.x * a1.x; q.y += a1.y * a1.y;
        } else { a1.x = 0.f; a1.y = 0.f; }
#pragma unroll
        for (int m = 16; m; m >>= 1) {
            s.x += __shfl_xor_sync(0xffffffffu, s.x, m);
            s.y += __shfl_xor_sync(0xffffffffu, s.y, m);
            q.x += __shfl_xor_sync(0xffffffffu, q.x, m);
            q.y += __shfl_xor_sync(0xffffffffu, q.y, m);
        }
        if (lane == 0) {
            float4* slot = (float4*)(red + ((pbase + p) * 2 + half) * 4);
            *slot = make_float4(s.x, s.y, q.x, q.y);
        }
        a0s[p] = a0; a1s[p] = a1;
    }
    __syncthreads();
#pragma unroll
    for (int p = 0; p < 4; p++) {
        float4 r0 = *(const float4*)(red + ((pbase + p) * 2 + 0) * 4);
        float4 r1 = *(const float4*)(red + ((pbase + p) * 2 + 1) * 4);
        const float inv = 1.0f / (float)H_SZ;
        float mx = (r0.x + r1.x) * inv, my = (r0.y + r1.y) * inv;
        float vx = (r0.z + r1.z) * inv - mx * mx;
        float vy = (r0.w + r1.w) * inv - my * my;
        float rx = rsqrtf(vx + 1e-5f), ry = rsqrtf(vy + 1e-5f);
        float g0 = vec[400 + j0], bt0 = vec[500 + j0];
        float w0 = vec[600 + j0];
        float2 d;
        d.x = ((a0s[p].x - mx) * rx * g0 + bt0) * w0;
        d.y = ((a0s[p].y - my) * ry * g0 + bt0) * w0;
        if (jv1) {
            float g1v = vec[400 + j1], bt1 = vec[500 + j1];
            float w1v = vec[600 + j1];
            d.x += ((a1s[p].x - mx) * rx * g1v + bt1) * w1v;
            d.y += ((a1s[p].y - my) * ry * g1v + bt1) * w1v;
        }
#pragma unroll
        for (int m = 16; m; m >>= 1) {
            d.x += __shfl_xor_sync(0xffffffffu, d.x, m);
            d.y += __shfl_xor_sync(0xffffffffu, d.y, m);
        }
        if (lane == 0) {
            float2* slot = (float2*)(head + ((pbase + p) * 2 + half) * 2);
            *slot = d;
        }
    }
    __syncthreads();
    if (tid < 64) {
        int rp = tid;
        float2 d0 = *(const float2*)(head + (rp * 2 + 0) * 2);
        float2 d1 = *(const float2*)(head + (rp * 2 + 1) * 2);
        float bov = vec[700];
        size_t base = (size_t)e * B_SZ + b0 + rp * 2;   // out[e*B + b]
        out[base]     = d0.x + d1.x + bov;
        out[base + 1] = d0.y + d1.y + bov;
    }
}

extern "C" void kernel_launch(void* const* d_in, const int* in_sizes, int n_in,
                              void* d_out, int out_size)
{
    const float* x   = (const float*)d_in[0];
    const float* W1  = (const float*)d_in[1];
    const float* b1  = (const float*)d_in[2];
    const float* g1  = (const float*)d_in[3];
    const float* be1 = (const float*)d_in[4];
    const float* W2  = (const float*)d_in[5];
    const float* b2  = (const float*)d_in[6];
    const float* g2  = (const float*)d_in[7];
    const float* be2 = (const float*)d_in[8];
    const float* Wo  = (const float*)d_in[9];
    const float* bo  = (const float*)d_in[10];
    float* out = (float*)d_out;

    const size_t smem = (size_t)SMEM_FLOATS * sizeof(float);   // ~176.4 KB
    cudaFuncSetAttribute(fused_edge_mlp_kernel,
                         cudaFuncAttributeMaxDynamicSharedMemorySize, (int)smem);

    dim3 grid(E_SZ, B_SZ / ROWS);   // (128, 32)
    fused_edge_mlp_kernel<<<grid, THREADS, smem>>>(
        x, W1, b1, g1, be1, W2, b2, g2, be2, Wo, bo, out);
}

// round 13
// speedup vs baseline: 1.0867x; 1.0867x over previous
#include <cuda_runtime.h>

typedef unsigned long long ull;

// Problem constants
#define B_SZ   4096
#define E_SZ   128
#define IP_SZ  64
#define H_SZ   100
#define ROWS   128      // batch rows per CTA
#define THREADS 512     // 16 warps, each: 4 row-pairs x 128 cols
#define XPS    66       // pair-stride of xP planes (ull units)
#define HPS    66       // pair-stride of hP2 (k-major) planes
#define W1S    66       // float stride of W1T rows (66 % 32 = 2 -> 2-way)
#define W2S    102      // float stride of W2T rows (102 % 32 = 6 -> 2-way)

// ---------- f32x2 packed helpers ----------
__device__ __forceinline__ ull pk2(float a, float b) {
    ull d;
    asm("mov.b64 %0, {%1, %2};" : "=l"(d) : "f"(a), "f"(b));
    return d;
}
__device__ __forceinline__ float2 upk2(ull v) {
    float2 r;
    asm("mov.b64 {%0, %1}, %2;" : "=f"(r.x), "=f"(r.y) : "l"(v));
    return r;
}
__device__ __forceinline__ ull ffma2(ull a, ull b, ull c) {
    ull d;
    asm("fma.rn.f32x2 %0, %1, %2, %3;" : "=l"(d) : "l"(a), "l"(b), "l"(c));
    return d;
}

// Per-pair epilogue: +bias, LeakyReLU(0.01), LayerNorm over the 100 real cols.
__device__ __forceinline__ void bias_leaky_ln_pair(
    const ull accp[4], const int j[4], const bool jv[4],
    const float* __restrict__ bias, const float* __restrict__ gam,
    const float* __restrict__ bet, float2 hv[4])
{
    float2 s = make_float2(0.f, 0.f);
    float2 q = make_float2(0.f, 0.f);
#pragma unroll
    for (int c = 0; c < 4; c++) {
        float2 a = upk2(accp[c]);
        if (jv[c]) {
            float bb = bias[j[c]];
            a.x += bb; a.y += bb;
            a.x = a.x > 0.f ? a.x : 0.01f * a.x;
            a.y = a.y > 0.f ? a.y : 0.01f * a.y;
            s.x += a.x; s.y += a.y;
            q.x += a.x * a.x; q.y += a.y * a.y;
        } else {
            a.x = 0.f; a.y = 0.f;
        }
        hv[c] = a;
    }
#pragma unroll
    for (int m = 16; m; m >>= 1) {
        s.x += __shfl_xor_sync(0xffffffffu, s.x, m);
        s.y += __shfl_xor_sync(0xffffffffu, s.y, m);
        q.x += __shfl_xor_sync(0xffffffffu, q.x, m);
        q.y += __shfl_xor_sync(0xffffffffu, q.y, m);
    }
    const float inv = 1.0f / (float)H_SZ;
    float mx = s.x * inv, my = s.y * inv;
    float vx = q.x * inv - mx * mx;
    float vy = q.y * inv - my * my;
    float rx = rsqrtf(vx + 1e-5f);
    float ry = rsqrtf(vy + 1e-5f);
#pragma unroll
    for (int c = 0; c < 4; c++) {
        if (jv[c]) {
            float g = gam[j[c]], bt = bet[j[c]];
            hv[c].x = (hv[c].x - mx) * rx * g + bt;
            hv[c].y = (hv[c].y - my) * ry * g + bt;
        }
    }
}

// Shared memory (floats), all segment sizes multiples of 4 (16B alignment):
//   W1T : 128*66   = 8448   (transposed, k-contiguous; rows j>=100 garbage-OK)
//   W2T : 128*102  = 13056  (transposed, k-contiguous)
//   vec : 704
//   xPf : 64*66*2  = 8448   (packed (even,odd) pair per (i, rp))
//   hPf : 100*66*2 = 13200  (k-major packed pairs: hP2[k][rp])
#define SMEM_FLOATS (8448 + 13056 + 704 + 8448 + 13200)

__global__ __launch_bounds__(THREADS, 1)
void fused_edge_mlp_kernel(
    const float* __restrict__ gx,  const float* __restrict__ gW1,
    const float* __restrict__ gb1, const float* __restrict__ gg1,
    const float* __restrict__ gbe1,const float* __restrict__ gW2,
    const float* __restrict__ gb2, const float* __restrict__ gg2,
    const float* __restrict__ gbe2,const float* __restrict__ gWo,
    const float* __restrict__ gbo, float* __restrict__ out)
{
    extern __shared__ float sm[];
    float* W1T = sm;                        // [128][66]
    float* W2T = W1T + 128 * W1S;           // [128][102]
    float* vec = W2T + 128 * W2S;           // 704
    float* xPf = vec + 704;                 // [64][66] pairs
    float* hPf = xPf + 64 * XPS * 2;        // [100][66] pairs (k-major)
    ull* xP  = (ull*)xPf;
    ull* hP2 = (ull*)hPf;

    const int e   = blockIdx.x;
    const int b0  = blockIdx.y * ROWS;
    const int tid = threadIdx.x;

    // ---- stage transposed weights (100 divides into 25 float4 per row) ----
    {
        const float4* w1v = (const float4*)(gW1 + (size_t)e * IP_SZ * H_SZ);
        for (int idx = tid; idx < IP_SZ * 25; idx += THREADS) {
            int i = idx / 25, c4 = idx % 25;
            float4 v = w1v[idx];
            int jj = c4 * 4;
            W1T[(jj + 0) * W1S + i] = v.x;
            W1T[(jj + 1) * W1S + i] = v.y;
            W1T[(jj + 2) * W1S + i] = v.z;
            W1T[(jj + 3) * W1S + i] = v.w;
        }
        const float4* w2v = (const float4*)(gW2 + (size_t)e * H_SZ * H_SZ);
        for (int idx = tid; idx < H_SZ * 25; idx += THREADS) {
            int k = idx / 25, c4 = idx % 25;
            float4 v = w2v[idx];
            int jj = c4 * 4;
            W2T[(jj + 0) * W2S + k] = v.x;
            W2T[(jj + 1) * W2S + k] = v.y;
            W2T[(jj + 2) * W2S + k] = v.z;
            W2T[(jj + 3) * W2S + k] = v.w;
        }
        if (tid < H_SZ) {
            vec[           tid] = gb1 [e * H_SZ + tid];
            vec[1 * H_SZ + tid] = gg1 [e * H_SZ + tid];
            vec[2 * H_SZ + tid] = gbe1[e * H_SZ + tid];
            vec[3 * H_SZ + tid] = gb2 [e * H_SZ + tid];
            vec[4 * H_SZ + tid] = gg2 [e * H_SZ + tid];
            vec[5 * H_SZ + tid] = gbe2[e * H_SZ + tid];
            vec[6 * H_SZ + tid] = gWo [e * H_SZ + tid];
        }
        if (tid == 0) vec[700] = gbo[e];

        // ---- stage x into packed (even,odd) row-pair planes: xP[i][rp] ----
        const float4* gx4 = (const float4*)gx;
        for (int idx = tid; idx < ROWS * 16; idx += THREADS) {
            int r = idx >> 4, i4 = idx & 15;
            float4 v = gx4[(((size_t)(b0 + r) * E_SZ + e) * IP_SZ >> 2) + i4];
            int rp = r >> 1, hr = r & 1;
            int i = i4 * 4;
            xPf[((i + 0) * XPS + rp) * 2 + hr] = v.x;
            xPf[((i + 1) * XPS + rp) * 2 + hr] = v.y;
            xPf[((i + 2) * XPS + rp) * 2 + hr] = v.z;
            xPf[((i + 3) * XPS + rp) * 2 + hr] = v.w;
        }
    }
    __syncthreads();

    const int warp  = tid >> 5;
    const int lane  = tid & 31;
    const int pbase = warp * 4;     // first row-pair of this warp

    int  j[4];
    bool jv[4];
#pragma unroll
    for (int c = 0; c < 4; c++) { j[c] = lane + 32 * c; jv[c] = (j[c] < H_SZ); }

    ull acc[4][4];
#pragma unroll
    for (int p = 0; p < 4; p++)
#pragma unroll
        for (int c = 0; c < 4; c++) acc[p][c] = 0ull;

    const float* w1l = W1T + lane * W1S;    // + c*(32*W1S) + i
    const float* w2l = W2T + lane * W2S;    // + c*(32*W2S) + k

    // ---- layer 1 mainloop: K=64, 2 k-steps per iter ----
#pragma unroll 4
    for (int i = 0; i < IP_SZ; i += 2) {
        ulonglong2 xa0 = *(const ulonglong2*)(xP + i * XPS + pbase);
        ulonglong2 xb0 = *(const ulonglong2*)(xP + i * XPS + pbase + 2);
        ulonglong2 xa1 = *(const ulonglong2*)(xP + (i + 1) * XPS + pbase);
        ulonglong2 xb1 = *(const ulonglong2*)(xP + (i + 1) * XPS + pbase + 2);
#pragma unroll
        for (int c = 0; c < 4; c++) {
            float2 wp = *(const float2*)(w1l + c * (32 * W1S) + i); // LDS.64
            ull wd0 = pk2(wp.x, wp.x);
            ull wd1 = pk2(wp.y, wp.y);
            acc[0][c] = ffma2(xa0.x, wd0, acc[0][c]);
            acc[1][c] = ffma2(xa0.y, wd0, acc[1][c]);
            acc[2][c] = ffma2(xb0.x, wd0, acc[2][c]);
            acc[3][c] = ffma2(xb0.y, wd0, acc[3][c]);
            acc[0][c] = ffma2(xa1.x, wd1, acc[0][c]);
            acc[1][c] = ffma2(xa1.y, wd1, acc[1][c]);
            acc[2][c] = ffma2(xb1.x, wd1, acc[2][c]);
            acc[3][c] = ffma2(xb1.y, wd1, acc[3][c]);
        }
    }

    // ---- layer-1 epilogue: bias + leaky + LN -> hP2 (k-major, warp-private) ----
#pragma unroll
    for (int p = 0; p < 4; p++) {
        float2 hv[4];
        bias_leaky_ln_pair(acc[p], j, jv, vec, vec + 100, vec + 200, hv);
#pragma unroll
        for (int c = 0; c < 4; c++) {
            if (jv[c])
                hP2[(size_t)j[c] * HPS + pbase + p] = pk2(hv[c].x, hv[c].y);
        }
#pragma unroll
        for (int c = 0; c < 4; c++) acc[p][c] = 0ull;
    }
    __syncwarp();   // hP2 slots for this warp's rps are warp-private

    // ---- layer 2 mainloop: K=100, 2 k-steps per iter ----
#pragma unroll 2
    for (int k = 0; k < H_SZ; k += 2) {
        ulonglong2 xa0 = *(const ulonglong2*)(hP2 + (size_t)k * HPS + pbase);
        ulonglong2 xb0 = *(const ulonglong2*)(hP2 + (size_t)k * HPS + pbase + 2);
        ulonglong2 xa1 = *(const ulonglong2*)(hP2 + (size_t)(k + 1) * HPS + pbase);
        ulonglong2 xb1 = *(const ulonglong2*)(hP2 + (size_t)(k + 1) * HPS + pbase + 2);
#pragma unroll
        for (int c = 0; c < 4; c++) {
            float2 wp = *(const float2*)(w2l + c * (32 * W2S) + k); // LDS.64
            ull wd0 = pk2(wp.x, wp.x);
            ull wd1 = pk2(wp.y, wp.y);
            acc[0][c] = ffma2(xa0.x, wd0, acc[0][c]);
            acc[1][c] = ffma2(xa0.y, wd0, acc[1][c]);
            acc[2][c] = ffma2(xb0.x, wd0, acc[2][c]);
            acc[3][c] = ffma2(xb0.y, wd0, acc[3][c]);
            acc[0][c] = ffma2(xa1.x, wd1, acc[0][c]);
            acc[1][c] = ffma2(xa1.y, wd1, acc[1][c]);
            acc[2][c] = ffma2(xb1.x, wd1, acc[2][c]);
            acc[3][c] = ffma2(xb1.y, wd1, acc[3][c]);
        }
    }

    // ---- layer-2 epilogue + head ----
#pragma unroll
    for (int p = 0; p < 4; p++) {
        float2 hv[4];
        bias_leaky_ln_pair(acc[p], j, jv, vec + 300, vec + 400, vec + 500, hv);

        float2 d = make_float2(0.f, 0.f);
#pragma unroll
        for (int c = 0; c < 4; c++) {
            if (jv[c]) {
                float wv = vec[600 + j[c]];
                d.x += hv[c].x * wv;
                d.y += hv[c].y * wv;
            }
        }
#pragma unroll
        for (int m = 16; m; m >>= 1) {
            d.x += __shfl_xor_sync(0xffffffffu, d.x, m);
            d.y += __shfl_xor_sync(0xffffffffu, d.y, m);
        }
        if (lane == 0) {
            float bov = vec[700];
            int r = (pbase + p) * 2;                   // local even row
            size_t base = (size_t)e * B_SZ + b0 + r;   // out[e*B + b]
            out[base]     = d.x + bov;
            out[base + 1] = d.y + bov;
        }
    }
}

extern "C" void kernel_launch(void* const* d_in, const int* in_sizes, int n_in,
                              void* d_out, int out_size)
{
    const float* x   = (const float*)d_in[0];
    const float* W1  = (const float*)d_in[1];
    const float* b1  = (const float*)d_in[2];
    const float* g1  = (const float*)d_in[3];
    const float* be1 = (const float*)d_in[4];
    const float* W2  = (const float*)d_in[5];
    const float* b2  = (const float*)d_in[6];
    const float* g2  = (const float*)d_in[7];
    const float* be2 = (const float*)d_in[8];
    const float* Wo  = (const float*)d_in[9];
    const float* bo  = (const float*)d_in[10];
    float* out = (float*)d_out;

    const size_t smem = (size_t)SMEM_FLOATS * sizeof(float);   // 175424 B
    cudaFuncSetAttribute(fused_edge_mlp_kernel,
                         cudaFuncAttributeMaxDynamicSharedMemorySize, (int)smem);

    dim3 grid(E_SZ, B_SZ / ROWS);   // (128, 32)
    fused_edge_mlp_kernel<<<grid, THREADS, smem>>>(
        x, W1, b1, g1, be1, W2, b2, g2, be2, Wo, bo, out);
}